// round 8
// baseline (speedup 1.0000x reference)
#include <cuda_runtime.h>
#include <cstdint>

typedef unsigned long long ull;

#define N_PTS 262144
#define K_CEN 512
#define D_DIM 128
#define MARGIN 0.006f

// scratch (device globals: allocation-free per harness rules)
__device__ float g_csq[K_CEN];
__device__ float g_ct[D_DIM * K_CEN];   // centroids transposed [d][k]
__device__ int   g_nflag;
__device__ int   g_flag[N_PTS];
__device__ ull   g_best[N_PTS];         // packed (distbits<<32)|k for flagged pts

// ---------------- packed f32x2 helpers (Blackwell FFMA2) ----------------
#define FMA2(d_, a_, b_) \
    asm("fma.rn.f32x2 %0, %1, %2, %0;" : "+l"(d_) : "l"(a_), "l"(b_))
#define ADD2(d_, a_, b_) \
    asm("add.rn.f32x2 %0, %1, %2;" : "=l"(d_) : "l"(a_), "l"(b_))
static __device__ __forceinline__ ull pack2(float lo, float hi) {
    ull r; asm("mov.b64 %0, {%1, %2};" : "=l"(r) : "f"(lo), "f"(hi)); return r;
}
static __device__ __forceinline__ float2 unpack2(ull v) {
    float2 r; asm("mov.b64 {%0, %1}, %2;" : "=f"(r.x), "=f"(r.y) : "l"(v)); return r;
}
static __device__ __forceinline__ ull dup2(float x) { return pack2(x, x); }

// ---------------- centroid norms (one warp per row) ----------------
__global__ void csq_kernel(const float* __restrict__ x) {
    int w = (blockIdx.x * blockDim.x + threadIdx.x) >> 5;
    int l = threadIdx.x & 31;
    if (w >= K_CEN) return;
    float4 v = *(const float4*)(x + (size_t)w * D_DIM + l * 4);
    float s = v.x * v.x + v.y * v.y + v.z * v.z + v.w * v.w;
    #pragma unroll
    for (int o = 16; o; o >>= 1) s += __shfl_xor_sync(0xffffffffu, s, o);
    if (l == 0) g_csq[w] = s;
}

// ---------------- centroid transpose: [512][128] -> g_ct [128][512] ----------
__global__ void transpose_c(const float* __restrict__ src) {
    if (blockIdx.x == 0 && blockIdx.y == 0 && threadIdx.x == 0) g_nflag = 0;
    __shared__ float t[32][33];
    int n0 = blockIdx.x * 32, d0 = blockIdx.y * 32;
    int tx = threadIdx.x & 31, ty = threadIdx.x >> 5;   // 256 thr: ty 0..7
    #pragma unroll
    for (int i = 0; i < 4; i++)
        t[ty + i * 8][tx] = src[(size_t)(n0 + ty + i * 8) * D_DIM + d0 + tx];
    __syncthreads();
    #pragma unroll
    for (int i = 0; i < 4; i++)
        g_ct[(size_t)(d0 + ty + i * 8) * K_CEN + n0 + tx] = t[tx][ty + i * 8];
}

// ---------------- main kernel ----------------
// CTA = 128 points (n) x 512 centroids (4 passes of 128 m), 256 threads.
// Thread tile: 8 m x 8 n; acc = f32x2[4 m-pairs][8 n].
// sXd [128 d][128 n DUPLICATED pairs] (128KB): B operands load as packed
// (x,x) pairs directly -> inner loop is pure FFMA2 + LDS (no dup/prmt work).
// sA [128 d][128 m] (64KB, reloaded per pass; reused for transpose + reduce).
#define SXD_F  (128 * 256)
#define SA_F   (128 * 128)
#define SMEM_BYTES ((SXD_F + SA_F + K_CEN + 128) * 4)

__global__ void __launch_bounds__(256, 1)
kmeans_main(const float* __restrict__ inp,
            float* __restrict__ dist_out, float* __restrict__ assign_out)
{
    extern __shared__ float sm[];
    float* sXd   = sm;                 // [d][2n] duplicated pairs
    float* sA    = sXd + SXD_F;        // [d][m] 128x128 (GEMM) / staging / reduce
    float* s_csq = sA + SA_F;          // 512
    float* s_xsq = s_csq + K_CEN;      // 128

    const int tid = threadIdx.x;
    const int tn = tid & 15, tm = tid >> 4;     // 16 n-threads x 16 m-threads
    const int n0 = blockIdx.x * 128;
    const int nl = tn * 8;                      // local col base (8 n per thread)

    // ---- load + transpose X tile into sXd[d][2n] (staging in sA space) ----
    {
        float (*stg)[33] = (float (*)[33])sA;          // 32x33 staging
        const int rr = tid >> 3, c4 = (tid & 7) * 4;   // read mapping
        const int wn = tid & 31, wg = tid >> 5;        // write mapping
        #pragma unroll
        for (int st = 0; st < 16; st++) {
            int sn = st & 3, sd = st >> 2;             // subtile: 32 n x 32 d
            float4 v = *(const float4*)(inp +
                (size_t)(n0 + sn * 32 + rr) * D_DIM + sd * 32 + c4);
            stg[rr][c4 + 0] = v.x; stg[rr][c4 + 1] = v.y;
            stg[rr][c4 + 2] = v.z; stg[rr][c4 + 3] = v.w;
            __syncthreads();
            #pragma unroll
            for (int j = 0; j < 4; j++) {
                float xv = stg[wn][wg * 4 + j];
                *(ull*)(sXd + (sd * 32 + wg * 4 + j) * 256 + 2 * (sn * 32 + wn))
                    = dup2(xv);
            }
            __syncthreads();
        }
        for (int i = tid; i < K_CEN; i += 256) s_csq[i] = g_csq[i];
        if (tid < 128) {                               // ||x||^2 from smem
            float s = 0.0f;
            #pragma unroll 8
            for (int d = 0; d < D_DIM; d++) {
                float v = sXd[d * 256 + 2 * tid];
                s = fmaf(v, v, s);
            }
            s_xsq[tid] = s;
        }
    }
    __syncthreads();

    float bd[8], bs[8];
    int   bk[8];
    #pragma unroll
    for (int j = 0; j < 8; j++) { bd[j] = 3.4e38f; bs[j] = 3.4e38f; bk[j] = 0; }

    const float* pA = sA + tm * 8;
    const float* pB = sXd + 2 * nl;

    for (int pass = 0; pass < 4; pass++) {
        const int m0 = pass * 128;
        if (pass) __syncthreads();   // all warps done reading sA of prev pass
        // load sA [128 d][128 m] from g_ct (L2-resident)
        #pragma unroll
        for (int i = 0; i < 16; i++) {
            int idx = tid + i * 256;
            int d = idx >> 5, mq = (idx & 31) * 4;
            *(float4*)(sA + d * 128 + mq) =
                *(const float4*)(g_ct + (size_t)d * K_CEN + m0 + mq);
        }
        __syncthreads();

        ull acc[4][8];
        #pragma unroll
        for (int mp = 0; mp < 4; mp++)
            #pragma unroll
            for (int j = 0; j < 8; j++) acc[mp][j] = 0ull;

        #pragma unroll 4
        for (int d = 0; d < D_DIM; d++) {
            ulonglong2 A0 = *(const ulonglong2*)(pA + d * 128);
            ulonglong2 A1 = *(const ulonglong2*)(pA + d * 128 + 4);
            ulonglong2 B0 = *(const ulonglong2*)(pB + d * 256);
            ulonglong2 B1 = *(const ulonglong2*)(pB + d * 256 + 4);
            ulonglong2 B2 = *(const ulonglong2*)(pB + d * 256 + 8);
            ulonglong2 B3 = *(const ulonglong2*)(pB + d * 256 + 12);
            FMA2(acc[0][0], A0.x, B0.x); FMA2(acc[1][0], A0.y, B0.x);
            FMA2(acc[2][0], A1.x, B0.x); FMA2(acc[3][0], A1.y, B0.x);
            FMA2(acc[0][1], A0.x, B0.y); FMA2(acc[1][1], A0.y, B0.y);
            FMA2(acc[2][1], A1.x, B0.y); FMA2(acc[3][1], A1.y, B0.y);
            FMA2(acc[0][2], A0.x, B1.x); FMA2(acc[1][2], A0.y, B1.x);
            FMA2(acc[2][2], A1.x, B1.x); FMA2(acc[3][2], A1.y, B1.x);
            FMA2(acc[0][3], A0.x, B1.y); FMA2(acc[1][3], A0.y, B1.y);
            FMA2(acc[2][3], A1.x, B1.y); FMA2(acc[3][3], A1.y, B1.y);
            FMA2(acc[0][4], A0.x, B2.x); FMA2(acc[1][4], A0.y, B2.x);
            FMA2(acc[2][4], A1.x, B2.x); FMA2(acc[3][4], A1.y, B2.x);
            FMA2(acc[0][5], A0.x, B2.y); FMA2(acc[1][5], A0.y, B2.y);
            FMA2(acc[2][5], A1.x, B2.y); FMA2(acc[3][5], A1.y, B2.y);
            FMA2(acc[0][6], A0.x, B3.x); FMA2(acc[1][6], A0.y, B3.x);
            FMA2(acc[2][6], A1.x, B3.x); FMA2(acc[3][6], A1.y, B3.x);
            FMA2(acc[0][7], A0.x, B3.y); FMA2(acc[1][7], A0.y, B3.y);
            FMA2(acc[2][7], A1.x, B3.y); FMA2(acc[3][7], A1.y, B3.y);
        }

        // ---- epilogue: distances out + running best/second ----
        ull xsd[8];
        #pragma unroll
        for (int j = 0; j < 8; j++) xsd[j] = dup2(s_xsq[nl + j]);
        const ull neg2 = pack2(-2.0f, -2.0f);

        #pragma unroll
        for (int mp = 0; mp < 4; mp++) {
            const int k0 = m0 + tm * 8 + mp * 2;
            ull cs2 = pack2(s_csq[k0], s_csq[k0 + 1]);
            #pragma unroll
            for (int q = 0; q < 2; q++) {
                float2 dv[4];
                #pragma unroll
                for (int jj = 0; jj < 4; jj++) {
                    int j = q * 4 + jj;
                    ull t; ADD2(t, cs2, xsd[j]);
                    FMA2(t, acc[mp][j], neg2);   // t = -2*dot + (c^2 + x^2)
                    dv[jj] = unpack2(t);
                }
                float4 v0 = make_float4(dv[0].x, dv[1].x, dv[2].x, dv[3].x);
                float4 v1 = make_float4(dv[0].y, dv[1].y, dv[2].y, dv[3].y);
                const size_t ng = (size_t)n0 + nl + q * 4;
                *(float4*)(dist_out + (size_t)k0 * N_PTS + ng) = v0;
                *(float4*)(dist_out + (size_t)(k0 + 1) * N_PTS + ng) = v1;
                #pragma unroll
                for (int jj = 0; jj < 4; jj++) {
                    int j = q * 4 + jj;
                    float va = dv[jj].x, vb = dv[jj].y;
                    if (va < bd[j]) { bs[j] = bd[j]; bd[j] = va; bk[j] = k0; }
                    else if (va < bs[j]) bs[j] = va;
                    if (vb < bd[j]) { bs[j] = bd[j]; bd[j] = vb; bk[j] = k0 + 1; }
                    else if (vb < bs[j]) bs[j] = vb;
                }
            }
        }
    }

    // ---- simple, auditable reduce: dump (bd,bs,bk) to padded smem, scan ----
    __syncthreads();   // everyone done reading sA (GEMM) -> reuse for reduce
    float2* s_rd = (float2*)sA;                 // [128 cols][17 pad]
    int*    s_rk = (int*)(s_rd + 128 * 17);     // [128 cols][17 pad]
    #pragma unroll
    for (int j = 0; j < 8; j++) {
        s_rd[(nl + j) * 17 + tm] = make_float2(bd[j], bs[j]);
        s_rk[(nl + j) * 17 + tm] = bk[j];
    }
    __syncthreads();
    if (tid < 128) {
        float d1 = 3.4e38f, d2 = 3.4e38f;
        int k1 = 0;
        #pragma unroll 4
        for (int i = 0; i < 16; i++) {
            float2 v = s_rd[tid * 17 + i];
            int kk = s_rk[tid * 17 + i];
            if (v.x < d1) { d2 = fminf(d1, v.y); d1 = v.x; k1 = kk; }
            else          { d2 = fminf(d2, v.x); }
        }
        int n = n0 + tid;
        assign_out[n] = (float)k1;
        if (d2 - d1 < MARGIN) {
            g_best[n] = ~0ull;
            __threadfence();
            int slot = atomicAdd(&g_nflag, 1);
            g_flag[slot] = n;
        }
    }
}

// ------ exact-enough refinement: compensated fp32 (NO fp64 on B300!) -------
// One warp per (flagged point, 32-centroid block): 16 warps/point -> short
// dependency chains; combine via global atomicMin on packed (distbits, k).
static __device__ __forceinline__ void comp_accum(float a, float b,
                                                  float& sum, float& comp,
                                                  float& lo) {
    float s   = __fsub_rn(a, b);
    float z   = __fsub_rn(s, a);
    float err = __fsub_rn(__fsub_rn(a, __fsub_rn(s, z)), __fadd_rn(b, z));
    float p   = __fmul_rn(s, s);
    float pe  = __fmaf_rn(s, s, -p);
    lo  = __fmaf_rn(__fadd_rn(s, s), err, lo);
    lo  = __fadd_rn(lo, pe);
    float t = __fadd_rn(sum, p);
    comp = __fadd_rn(comp, __fadd_rn(__fsub_rn(sum, t), p));
    sum = t;
}

__global__ void __launch_bounds__(256, 2)
refine_kernel(const float* __restrict__ inp, const float* __restrict__ cen)
{
    __shared__ float sx[8][D_DIM];
    const int wid = threadIdx.x >> 5, l = threadIdx.x & 31;
    const int gw = blockIdx.x * 8 + wid;
    const int nW = gridDim.x * 8;
    const int nwork = g_nflag * 16;             // 16 warps per point
    for (int it = gw; it < nwork; it += nW) {
        const int fi = it >> 4, jb = it & 15;
        const int n = g_flag[fi];
        for (int d = l; d < D_DIM; d += 32)
            sx[wid][d] = inp[(size_t)n * D_DIM + d];
        __syncwarp();
        const int k = jb * 32 + l;
        const float4* c4 = (const float4*)(cen + (size_t)k * D_DIM);
        float sum = 0.0f, comp = 0.0f, lo = 0.0f;
        #pragma unroll 8
        for (int d4 = 0; d4 < D_DIM / 4; d4++) {
            float4 cv = __ldg(c4 + d4);
            const float* xp = &sx[wid][d4 * 4];
            comp_accum(xp[0], cv.x, sum, comp, lo);
            comp_accum(xp[1], cv.y, sum, comp, lo);
            comp_accum(xp[2], cv.z, sum, comp, lo);
            comp_accum(xp[3], cv.w, sum, comp, lo);
        }
        float dist = __fadd_rn(sum, __fadd_rn(comp, lo));
        ull e = ((ull)__float_as_uint(dist) << 32) | (unsigned)k;
        #pragma unroll
        for (int off = 16; off; off >>= 1) {
            ull oe = __shfl_xor_sync(0xffffffffu, e, off);
            if (oe < e) e = oe;
        }
        if (l == 0) atomicMin(&g_best[n], e);
        __syncwarp();
    }
}

__global__ void writeback_kernel(float* __restrict__ assign_out) {
    const int nf = g_nflag;
    for (int i = blockIdx.x * blockDim.x + threadIdx.x; i < nf;
         i += gridDim.x * blockDim.x) {
        int n = g_flag[i];
        assign_out[n] = (float)(unsigned)(g_best[n] & 0xffffffffu);
    }
}

// ---------------- launch ----------------
extern "C" void kernel_launch(void* const* d_in, const int* in_sizes, int n_in,
                              void* d_out, int out_size) {
    const float* inp = (const float*)d_in[0];
    const float* cen = (const float*)d_in[1];
    float* dist = (float*)d_out;
    long long need = (long long)K_CEN * N_PTS + N_PTS;
    float* assign = ((long long)out_size >= need) ? dist + (size_t)K_CEN * N_PTS
                                                  : dist;  // fallback, unused

    cudaFuncSetAttribute(kmeans_main, cudaFuncAttributeMaxDynamicSharedMemorySize,
                         SMEM_BYTES);

    transpose_c<<<dim3(K_CEN / 32, D_DIM / 32), 256>>>(cen);  // + zero flag ctr
    csq_kernel<<<K_CEN / 8, 256>>>(cen);                      // ||c||^2
    kmeans_main<<<N_PTS / 128, 256, SMEM_BYTES>>>(inp, dist, assign);
    refine_kernel<<<148, 256>>>(inp, cen);
    writeback_kernel<<<8, 256>>>(assign);
}

// round 9
// speedup vs baseline: 2.0588x; 2.0588x over previous
#include <cuda_runtime.h>
#include <cstdint>

typedef unsigned long long ull;

#define N_PTS 262144
#define K_CEN 512
#define D_DIM 128
#define MARGIN 0.006f

// scratch (device globals: allocation-free per harness rules)
__device__ float g_csq[K_CEN];
__device__ float g_ct[D_DIM * K_CEN];   // centroids transposed [d][k]
__device__ int   g_nflag;
__device__ int   g_flag[N_PTS];
__device__ ull   g_best[N_PTS];         // packed (distbits<<32)|k for flagged pts

// ---------------- packed f32x2 helpers (Blackwell FFMA2) ----------------
#define FMA2(d_, a_, b_) \
    asm("fma.rn.f32x2 %0, %1, %2, %0;" : "+l"(d_) : "l"(a_), "l"(b_))
#define ADD2(d_, a_, b_) \
    asm("add.rn.f32x2 %0, %1, %2;" : "=l"(d_) : "l"(a_), "l"(b_))
static __device__ __forceinline__ ull pack2(float lo, float hi) {
    ull r; asm("mov.b64 %0, {%1, %2};" : "=l"(r) : "f"(lo), "f"(hi)); return r;
}
static __device__ __forceinline__ float2 unpack2(ull v) {
    float2 r; asm("mov.b64 {%0, %1}, %2;" : "=f"(r.x), "=f"(r.y) : "l"(v)); return r;
}
// broadcast-duplicate via PRMT (alu pipe, keeps fma pipe pure FFMA2)
static __device__ __forceinline__ ull dup2(float x) {
    ull r; uint32_t xi = __float_as_uint(x);
    asm("{\n\t.reg .b32 lo, hi;\n\t"
        "prmt.b32 lo, %1, %1, 0x3210;\n\t"
        "prmt.b32 hi, %1, %1, 0x7654;\n\t"
        "mov.b64 %0, {lo, hi};\n\t}"
        : "=l"(r) : "r"(xi));
    return r;
}

// ---------------- centroid norms (one warp per row) ----------------
__global__ void csq_kernel(const float* __restrict__ x) {
    int w = (blockIdx.x * blockDim.x + threadIdx.x) >> 5;
    int l = threadIdx.x & 31;
    if (w >= K_CEN) return;
    float4 v = *(const float4*)(x + (size_t)w * D_DIM + l * 4);
    float s = v.x * v.x + v.y * v.y + v.z * v.z + v.w * v.w;
    #pragma unroll
    for (int o = 16; o; o >>= 1) s += __shfl_xor_sync(0xffffffffu, s, o);
    if (l == 0) g_csq[w] = s;
}

// ---------------- centroid transpose: [512][128] -> g_ct [128][512] ----------
__global__ void transpose_c(const float* __restrict__ src) {
    if (blockIdx.x == 0 && blockIdx.y == 0 && threadIdx.x == 0) g_nflag = 0;
    __shared__ float t[32][33];
    int n0 = blockIdx.x * 32, d0 = blockIdx.y * 32;
    int tx = threadIdx.x & 31, ty = threadIdx.x >> 5;   // 256 thr: ty 0..7
    #pragma unroll
    for (int i = 0; i < 4; i++)
        t[ty + i * 8][tx] = src[(size_t)(n0 + ty + i * 8) * D_DIM + d0 + tx];
    __syncthreads();
    #pragma unroll
    for (int i = 0; i < 4; i++)
        g_ct[(size_t)(d0 + ty + i * 8) * K_CEN + n0 + tx] = t[tx][ty + i * 8];
}

// ---------------- main kernel (R7 configuration — measured best) ----------
// CTA = 128 points (n) x 512 centroids (2 passes of 256 m), 512 threads.
// Thread tile: 8 m x 8 n; acc = f32x2[4 m-pairs][8 n].
// smem: sX [128 d][128 n] (64KB), sA [128 d][256 m] (128KB, reused for reduce).
#define SX_F   (128 * 128)
#define SA_F   (128 * 256)
#define SMEM_BYTES ((SX_F + SA_F + K_CEN + 128) * 4)

__global__ void __launch_bounds__(512, 1)
kmeans_main(const float* __restrict__ inp,
            float* __restrict__ dist_out, float* __restrict__ assign_out)
{
    extern __shared__ float sm[];
    float* sX    = sm;                 // [d][n] 128x128
    float* sA    = sX + SX_F;          // [d][m] 128x256 (GEMM) / reduce arrays
    float* s_csq = sA + SA_F;          // 512
    float* s_xsq = s_csq + K_CEN;      // 128

    const int tid = threadIdx.x;
    const int tn = tid & 15, tm = tid >> 4;     // 16 n-threads x 32 m-threads
    const int n0 = blockIdx.x * 128;
    const int nl = tn * 8;                      // local col base (8 n per thread)

    // ---- load + transpose X tile into sX[d][n] (staging in sA space) ----
    {
        float (*stg)[33] = (float (*)[33])sA;          // 64x33 staging
        const int r = tid >> 3, c4 = (tid & 7) * 4;    // read mapping
        const int tx = tid & 63, rg = tid >> 6;        // write mapping
        #pragma unroll
        for (int st = 0; st < 8; st++) {
            int sn = st & 1, sd = st >> 1;             // subtile: 64 n x 32 d
            float4 v = *(const float4*)(inp +
                (size_t)(n0 + sn * 64 + r) * D_DIM + sd * 32 + c4);
            stg[r][c4 + 0] = v.x; stg[r][c4 + 1] = v.y;
            stg[r][c4 + 2] = v.z; stg[r][c4 + 3] = v.w;
            __syncthreads();
            #pragma unroll
            for (int j = 0; j < 4; j++)
                sX[(sd * 32 + rg * 4 + j) * 128 + sn * 64 + tx] = stg[tx][rg * 4 + j];
            __syncthreads();
        }
        if (tid < K_CEN) s_csq[tid] = g_csq[tid];
        if (tid < 128) {                               // ||x||^2 from smem
            float s = 0.0f;
            #pragma unroll 8
            for (int d = 0; d < D_DIM; d++) {
                float v = sX[d * 128 + tid];
                s = fmaf(v, v, s);
            }
            s_xsq[tid] = s;
        }
    }
    __syncthreads();

    float bd[8], bs[8];
    int   bk[8];
    #pragma unroll
    for (int j = 0; j < 8; j++) { bd[j] = 3.4e38f; bs[j] = 3.4e38f; bk[j] = 0; }

    const float* pA = sA + tm * 8;
    const float* pB = sX + nl;

    for (int pass = 0; pass < 2; pass++) {
        const int m0 = pass * 256;
        if (pass) __syncthreads();   // all warps done reading sA of pass 0
        // load sA [128 d][256 m] from g_ct (L2-resident)
        #pragma unroll
        for (int i = 0; i < 16; i++) {
            int idx = tid + i * 512;
            int d = idx >> 6, mq = (idx & 63) * 4;
            *(float4*)(sA + d * 256 + mq) =
                *(const float4*)(g_ct + (size_t)d * K_CEN + m0 + mq);
        }
        __syncthreads();

        ull acc[4][8];
        #pragma unroll
        for (int mp = 0; mp < 4; mp++)
            #pragma unroll
            for (int j = 0; j < 8; j++) acc[mp][j] = 0ull;

        #pragma unroll 4
        for (int d = 0; d < D_DIM; d++) {
            ulonglong2 A0 = *(const ulonglong2*)(pA + d * 256);
            ulonglong2 A1 = *(const ulonglong2*)(pA + d * 256 + 4);
            float4 b0 = *(const float4*)(pB + d * 128);
            float4 b1 = *(const float4*)(pB + d * 128 + 4);
            ull u;
            u = dup2(b0.x);
            FMA2(acc[0][0], A0.x, u); FMA2(acc[1][0], A0.y, u);
            FMA2(acc[2][0], A1.x, u); FMA2(acc[3][0], A1.y, u);
            u = dup2(b0.y);
            FMA2(acc[0][1], A0.x, u); FMA2(acc[1][1], A0.y, u);
            FMA2(acc[2][1], A1.x, u); FMA2(acc[3][1], A1.y, u);
            u = dup2(b0.z);
            FMA2(acc[0][2], A0.x, u); FMA2(acc[1][2], A0.y, u);
            FMA2(acc[2][2], A1.x, u); FMA2(acc[3][2], A1.y, u);
            u = dup2(b0.w);
            FMA2(acc[0][3], A0.x, u); FMA2(acc[1][3], A0.y, u);
            FMA2(acc[2][3], A1.x, u); FMA2(acc[3][3], A1.y, u);
            u = dup2(b1.x);
            FMA2(acc[0][4], A0.x, u); FMA2(acc[1][4], A0.y, u);
            FMA2(acc[2][4], A1.x, u); FMA2(acc[3][4], A1.y, u);
            u = dup2(b1.y);
            FMA2(acc[0][5], A0.x, u); FMA2(acc[1][5], A0.y, u);
            FMA2(acc[2][5], A1.x, u); FMA2(acc[3][5], A1.y, u);
            u = dup2(b1.z);
            FMA2(acc[0][6], A0.x, u); FMA2(acc[1][6], A0.y, u);
            FMA2(acc[2][6], A1.x, u); FMA2(acc[3][6], A1.y, u);
            u = dup2(b1.w);
            FMA2(acc[0][7], A0.x, u); FMA2(acc[1][7], A0.y, u);
            FMA2(acc[2][7], A1.x, u); FMA2(acc[3][7], A1.y, u);
        }

        // ---- epilogue: distances out + running best/second ----
        ull xsd[8];
        #pragma unroll
        for (int j = 0; j < 8; j++) xsd[j] = dup2(s_xsq[nl + j]);
        const ull neg2 = pack2(-2.0f, -2.0f);

        #pragma unroll
        for (int mp = 0; mp < 4; mp++) {
            const int k0 = m0 + tm * 8 + mp * 2;
            ull cs2 = pack2(s_csq[k0], s_csq[k0 + 1]);
            #pragma unroll
            for (int q = 0; q < 2; q++) {
                float2 dv[4];
                #pragma unroll
                for (int jj = 0; jj < 4; jj++) {
                    int j = q * 4 + jj;
                    ull t; ADD2(t, cs2, xsd[j]);
                    FMA2(t, acc[mp][j], neg2);   // t = -2*dot + (c^2 + x^2)
                    dv[jj] = unpack2(t);
                }
                float4 v0 = make_float4(dv[0].x, dv[1].x, dv[2].x, dv[3].x);
                float4 v1 = make_float4(dv[0].y, dv[1].y, dv[2].y, dv[3].y);
                const size_t ng = (size_t)n0 + nl + q * 4;
                *(float4*)(dist_out + (size_t)k0 * N_PTS + ng) = v0;
                *(float4*)(dist_out + (size_t)(k0 + 1) * N_PTS + ng) = v1;
                #pragma unroll
                for (int jj = 0; jj < 4; jj++) {
                    int j = q * 4 + jj;
                    float va = dv[jj].x, vb = dv[jj].y;
                    if (va < bd[j]) { bs[j] = bd[j]; bd[j] = va; bk[j] = k0; }
                    else if (va < bs[j]) bs[j] = va;
                    if (vb < bd[j]) { bs[j] = bd[j]; bd[j] = vb; bk[j] = k0 + 1; }
                    else if (vb < bs[j]) bs[j] = vb;
                }
            }
        }
    }

    // ---- simple, auditable reduce: dump (bd,bs,bk) to padded smem, scan ----
    __syncthreads();   // everyone done reading sA (GEMM) -> reuse for reduce
    float2* s_rd = (float2*)sA;                 // [128 cols][33 pad]
    int*    s_rk = (int*)(s_rd + 128 * 33);     // [128 cols][33 pad]
    #pragma unroll
    for (int j = 0; j < 8; j++) {
        s_rd[(nl + j) * 33 + tm] = make_float2(bd[j], bs[j]);
        s_rk[(nl + j) * 33 + tm] = bk[j];
    }
    __syncthreads();
    if (tid < 128) {
        float d1 = 3.4e38f, d2 = 3.4e38f;
        int k1 = 0;
        #pragma unroll 4
        for (int i = 0; i < 32; i++) {
            float2 v = s_rd[tid * 33 + i];
            int kk = s_rk[tid * 33 + i];
            if (v.x < d1) { d2 = fminf(d1, v.y); d1 = v.x; k1 = kk; }
            else          { d2 = fminf(d2, v.x); }
        }
        int n = n0 + tid;
        assign_out[n] = (float)k1;
        if (d2 - d1 < MARGIN) {
            g_best[n] = ~0ull;
            __threadfence();
            int slot = atomicAdd(&g_nflag, 1);
            g_flag[slot] = n;
        }
    }
}

// ------ exact-enough refinement: compensated fp32 (NO fp64 on B300!) -------
// One warp per (flagged point, 32-centroid block): 16 warps/point -> short
// dependency chains; combine via global atomicMin on packed (distbits, k).
static __device__ __forceinline__ void comp_accum(float a, float b,
                                                  float& sum, float& comp,
                                                  float& lo) {
    float s   = __fsub_rn(a, b);
    float z   = __fsub_rn(s, a);
    float err = __fsub_rn(__fsub_rn(a, __fsub_rn(s, z)), __fadd_rn(b, z));
    float p   = __fmul_rn(s, s);
    float pe  = __fmaf_rn(s, s, -p);
    lo  = __fmaf_rn(__fadd_rn(s, s), err, lo);
    lo  = __fadd_rn(lo, pe);
    float t = __fadd_rn(sum, p);
    comp = __fadd_rn(comp, __fadd_rn(__fsub_rn(sum, t), p));
    sum = t;
}

__global__ void __launch_bounds__(256, 2)
refine_kernel(const float* __restrict__ inp, const float* __restrict__ cen)
{
    __shared__ float sx[8][D_DIM];
    const int wid = threadIdx.x >> 5, l = threadIdx.x & 31;
    const int gw = blockIdx.x * 8 + wid;
    const int nW = gridDim.x * 8;
    const int nwork = g_nflag * 16;             // 16 warps per point
    for (int it = gw; it < nwork; it += nW) {
        const int fi = it >> 4, jb = it & 15;
        const int n = g_flag[fi];
        for (int d = l; d < D_DIM; d += 32)
            sx[wid][d] = inp[(size_t)n * D_DIM + d];
        __syncwarp();
        const int k = jb * 32 + l;
        const float4* c4 = (const float4*)(cen + (size_t)k * D_DIM);
        float sum = 0.0f, comp = 0.0f, lo = 0.0f;
        #pragma unroll 8
        for (int d4 = 0; d4 < D_DIM / 4; d4++) {
            float4 cv = __ldg(c4 + d4);
            const float* xp = &sx[wid][d4 * 4];
            comp_accum(xp[0], cv.x, sum, comp, lo);
            comp_accum(xp[1], cv.y, sum, comp, lo);
            comp_accum(xp[2], cv.z, sum, comp, lo);
            comp_accum(xp[3], cv.w, sum, comp, lo);
        }
        float dist = __fadd_rn(sum, __fadd_rn(comp, lo));
        ull e = ((ull)__float_as_uint(dist) << 32) | (unsigned)k;
        #pragma unroll
        for (int off = 16; off; off >>= 1) {
            ull oe = __shfl_xor_sync(0xffffffffu, e, off);
            if (oe < e) e = oe;
        }
        if (l == 0) atomicMin(&g_best[n], e);
        __syncwarp();
    }
}

__global__ void writeback_kernel(float* __restrict__ assign_out) {
    const int nf = g_nflag;
    for (int i = blockIdx.x * blockDim.x + threadIdx.x; i < nf;
         i += gridDim.x * blockDim.x) {
        int n = g_flag[i];
        assign_out[n] = (float)(unsigned)(g_best[n] & 0xffffffffu);
    }
}

// ---------------- launch ----------------
extern "C" void kernel_launch(void* const* d_in, const int* in_sizes, int n_in,
                              void* d_out, int out_size) {
    const float* inp = (const float*)d_in[0];
    const float* cen = (const float*)d_in[1];
    float* dist = (float*)d_out;
    long long need = (long long)K_CEN * N_PTS + N_PTS;
    float* assign = ((long long)out_size >= need) ? dist + (size_t)K_CEN * N_PTS
                                                  : dist;  // fallback, unused

    cudaFuncSetAttribute(kmeans_main, cudaFuncAttributeMaxDynamicSharedMemorySize,
                         SMEM_BYTES);

    transpose_c<<<dim3(K_CEN / 32, D_DIM / 32), 256>>>(cen);  // + zero flag ctr
    csq_kernel<<<K_CEN / 8, 256>>>(cen);                      // ||c||^2
    kmeans_main<<<N_PTS / 128, 512, SMEM_BYTES>>>(inp, dist, assign);
    refine_kernel<<<148, 256>>>(inp, cen);
    writeback_kernel<<<8, 256>>>(assign);
}

// round 10
// speedup vs baseline: 2.0944x; 1.0173x over previous
#include <cuda_runtime.h>
#include <cstdint>

typedef unsigned long long ull;

#define N_PTS 262144
#define K_CEN 512
#define D_DIM 128
#define MARGIN 0.006f

// scratch (device globals: allocation-free per harness rules)
__device__ float g_csq[K_CEN];
__device__ float g_ct[D_DIM * K_CEN];   // centroids transposed [d][k]
__device__ int   g_nflag;
__device__ int   g_flag[N_PTS];
__device__ ull   g_best[N_PTS];         // packed (distbits<<32)|k for flagged pts

// ---------------- packed f32x2 helpers (Blackwell FFMA2) ----------------
#define FMA2(d_, a_, b_) \
    asm("fma.rn.f32x2 %0, %1, %2, %0;" : "+l"(d_) : "l"(a_), "l"(b_))
#define ADD2(d_, a_, b_) \
    asm("add.rn.f32x2 %0, %1, %2;" : "=l"(d_) : "l"(a_), "l"(b_))
static __device__ __forceinline__ ull pack2(float lo, float hi) {
    ull r; asm("mov.b64 %0, {%1, %2};" : "=l"(r) : "f"(lo), "f"(hi)); return r;
}
static __device__ __forceinline__ float2 unpack2(ull v) {
    float2 r; asm("mov.b64 {%0, %1}, %2;" : "=f"(r.x), "=f"(r.y) : "l"(v)); return r;
}
// broadcast-duplicate via PRMT (alu pipe, keeps fma pipe pure FFMA2)
static __device__ __forceinline__ ull dup2(float x) {
    ull r; uint32_t xi = __float_as_uint(x);
    asm("{\n\t.reg .b32 lo, hi;\n\t"
        "prmt.b32 lo, %1, %1, 0x3210;\n\t"
        "prmt.b32 hi, %1, %1, 0x7654;\n\t"
        "mov.b64 %0, {lo, hi};\n\t}"
        : "=l"(r) : "r"(xi));
    return r;
}

// ---------------- centroid norms (one warp per row) ----------------
__global__ void csq_kernel(const float* __restrict__ x) {
    int w = (blockIdx.x * blockDim.x + threadIdx.x) >> 5;
    int l = threadIdx.x & 31;
    if (w >= K_CEN) return;
    float4 v = *(const float4*)(x + (size_t)w * D_DIM + l * 4);
    float s = v.x * v.x + v.y * v.y + v.z * v.z + v.w * v.w;
    #pragma unroll
    for (int o = 16; o; o >>= 1) s += __shfl_xor_sync(0xffffffffu, s, o);
    if (l == 0) g_csq[w] = s;
}

// ---------------- centroid transpose: [512][128] -> g_ct [128][512] ----------
__global__ void transpose_c(const float* __restrict__ src) {
    if (blockIdx.x == 0 && blockIdx.y == 0 && threadIdx.x == 0) g_nflag = 0;
    __shared__ float t[32][33];
    int n0 = blockIdx.x * 32, d0 = blockIdx.y * 32;
    int tx = threadIdx.x & 31, ty = threadIdx.x >> 5;   // 256 thr: ty 0..7
    #pragma unroll
    for (int i = 0; i < 4; i++)
        t[ty + i * 8][tx] = src[(size_t)(n0 + ty + i * 8) * D_DIM + d0 + tx];
    __syncthreads();
    #pragma unroll
    for (int i = 0; i < 4; i++)
        g_ct[(size_t)(d0 + ty + i * 8) * K_CEN + n0 + tx] = t[tx][ty + i * 8];
}

// ---------------- main kernel ----------------
// CTA = 128 points (n) x 512 centroids (2 passes of 256 m), 512 threads.
// Thread tile: 8 m x 8 n; acc = f32x2[4 m-pairs][8 n].
// smem: sX [128 d][128 n] (64KB), sA [128 d][256 m] (128KB, reused for reduce).
#define SX_F   (128 * 128)
#define SA_F   (128 * 256)
#define SMEM_BYTES ((SX_F + SA_F + K_CEN + 128) * 4)

__global__ void __launch_bounds__(512, 1)
kmeans_main(const float* __restrict__ inp,
            float* __restrict__ dist_out, float* __restrict__ assign_out)
{
    extern __shared__ float sm[];
    float* sX    = sm;                 // [d][n] 128x128
    float* sA    = sX + SX_F;          // [d][m] 128x256 (GEMM) / reduce arrays
    float* s_csq = sA + SA_F;          // 512
    float* s_xsq = s_csq + K_CEN;      // 128

    const int tid = threadIdx.x;
    const int tn = tid & 15, tm = tid >> 4;     // 16 n-threads x 32 m-threads
    const int n0 = blockIdx.x * 128;
    const int nl = tn * 8;                      // local col base (8 n per thread)

    // ---- prologue: MLP-preload X tile, derive ||x||^2, transpose to sX ----
    {
        const int r = tid >> 3, c4 = (tid & 7) * 4;    // read mapping
        const int tx = tid & 63, rg = tid >> 6;        // write mapping
        float4 vreg[8];
        #pragma unroll
        for (int st = 0; st < 8; st++) {               // 8 LDGs in flight
            int sn = st & 1, sd = st >> 1;             // subtile: 64 n x 32 d
            vreg[st] = *(const float4*)(inp +
                (size_t)(n0 + sn * 64 + r) * D_DIM + sd * 32 + c4);
        }
        float csqv = g_csq[tid];                       // early LDG (tid<512=K_CEN)

        // ||x||^2 partials from registers: even st -> row r, odd -> row r+64
        float px0 = 0.0f, px1 = 0.0f;
        #pragma unroll
        for (int st = 0; st < 8; st++) {
            float4 v = vreg[st];
            float s = fmaf(v.x, v.x, fmaf(v.y, v.y, fmaf(v.z, v.z, v.w * v.w)));
            if (st & 1) px1 += s; else px0 += s;
        }
        #pragma unroll
        for (int off = 1; off <= 4; off <<= 1) {       // sum over 8-lane c4 group
            px0 += __shfl_xor_sync(0xffffffffu, px0, off);
            px1 += __shfl_xor_sync(0xffffffffu, px1, off);
        }

        float (*stg)[33] = (float (*)[33])sA;          // 64x33 staging
        #pragma unroll
        for (int st = 0; st < 8; st++) {
            int sn = st & 1, sd = st >> 1;
            stg[r][c4 + 0] = vreg[st].x; stg[r][c4 + 1] = vreg[st].y;
            stg[r][c4 + 2] = vreg[st].z; stg[r][c4 + 3] = vreg[st].w;
            __syncthreads();
            #pragma unroll
            for (int j = 0; j < 4; j++)
                sX[(sd * 32 + rg * 4 + j) * 128 + sn * 64 + tx] = stg[tx][rg * 4 + j];
            __syncthreads();
        }
        s_csq[tid] = csqv;
        if ((tid & 7) == 0) {                          // lane leader of c4 group
            s_xsq[r] = px0;
            s_xsq[r + 64] = px1;
        }
    }
    __syncthreads();

    float bd[8], bs[8];
    int   bk[8];
    #pragma unroll
    for (int j = 0; j < 8; j++) { bd[j] = 3.4e38f; bs[j] = 3.4e38f; bk[j] = 0; }

    const float* pA = sA + tm * 8;
    const float* pB = sX + nl;

    for (int pass = 0; pass < 2; pass++) {
        const int m0 = pass * 256;
        // prefetch first half of sA chunk BEFORE the sync (no smem touched):
        // for pass 1 these LDGs overlap other warps' pass-0 compute/epilogue.
        float4 pf[8];
        #pragma unroll
        for (int i = 0; i < 8; i++) {
            int idx = tid + i * 512;
            int d = idx >> 6, mq = (idx & 63) * 4;
            pf[i] = *(const float4*)(g_ct + (size_t)d * K_CEN + m0 + mq);
        }
        if (pass) __syncthreads();   // all warps done reading sA of pass 0
        #pragma unroll
        for (int i = 0; i < 8; i++) {
            int idx = tid + i * 512;
            int d = idx >> 6, mq = (idx & 63) * 4;
            *(float4*)(sA + d * 256 + mq) = pf[i];
        }
        #pragma unroll
        for (int i = 8; i < 16; i++) {
            int idx = tid + i * 512;
            int d = idx >> 6, mq = (idx & 63) * 4;
            *(float4*)(sA + d * 256 + mq) =
                *(const float4*)(g_ct + (size_t)d * K_CEN + m0 + mq);
        }
        __syncthreads();

        ull acc[4][8];
        #pragma unroll
        for (int mp = 0; mp < 4; mp++)
            #pragma unroll
            for (int j = 0; j < 8; j++) acc[mp][j] = 0ull;

        #pragma unroll 4
        for (int d = 0; d < D_DIM; d++) {
            ulonglong2 A0 = *(const ulonglong2*)(pA + d * 256);
            ulonglong2 A1 = *(const ulonglong2*)(pA + d * 256 + 4);
            float4 b0 = *(const float4*)(pB + d * 128);
            float4 b1 = *(const float4*)(pB + d * 128 + 4);
            ull u;
            u = dup2(b0.x);
            FMA2(acc[0][0], A0.x, u); FMA2(acc[1][0], A0.y, u);
            FMA2(acc[2][0], A1.x, u); FMA2(acc[3][0], A1.y, u);
            u = dup2(b0.y);
            FMA2(acc[0][1], A0.x, u); FMA2(acc[1][1], A0.y, u);
            FMA2(acc[2][1], A1.x, u); FMA2(acc[3][1], A1.y, u);
            u = dup2(b0.z);
            FMA2(acc[0][2], A0.x, u); FMA2(acc[1][2], A0.y, u);
            FMA2(acc[2][2], A1.x, u); FMA2(acc[3][2], A1.y, u);
            u = dup2(b0.w);
            FMA2(acc[0][3], A0.x, u); FMA2(acc[1][3], A0.y, u);
            FMA2(acc[2][3], A1.x, u); FMA2(acc[3][3], A1.y, u);
            u = dup2(b1.x);
            FMA2(acc[0][4], A0.x, u); FMA2(acc[1][4], A0.y, u);
            FMA2(acc[2][4], A1.x, u); FMA2(acc[3][4], A1.y, u);
            u = dup2(b1.y);
            FMA2(acc[0][5], A0.x, u); FMA2(acc[1][5], A0.y, u);
            FMA2(acc[2][5], A1.x, u); FMA2(acc[3][5], A1.y, u);
            u = dup2(b1.z);
            FMA2(acc[0][6], A0.x, u); FMA2(acc[1][6], A0.y, u);
            FMA2(acc[2][6], A1.x, u); FMA2(acc[3][6], A1.y, u);
            u = dup2(b1.w);
            FMA2(acc[0][7], A0.x, u); FMA2(acc[1][7], A0.y, u);
            FMA2(acc[2][7], A1.x, u); FMA2(acc[3][7], A1.y, u);
        }

        // ---- epilogue: distances out + running best/second ----
        ull xsd[8];
        #pragma unroll
        for (int j = 0; j < 8; j++) xsd[j] = dup2(s_xsq[nl + j]);
        const ull neg2 = pack2(-2.0f, -2.0f);

        #pragma unroll
        for (int mp = 0; mp < 4; mp++) {
            const int k0 = m0 + tm * 8 + mp * 2;
            ull cs2 = pack2(s_csq[k0], s_csq[k0 + 1]);
            #pragma unroll
            for (int q = 0; q < 2; q++) {
                float2 dv[4];
                #pragma unroll
                for (int jj = 0; jj < 4; jj++) {
                    int j = q * 4 + jj;
                    ull t; ADD2(t, cs2, xsd[j]);
                    FMA2(t, acc[mp][j], neg2);   // t = -2*dot + (c^2 + x^2)
                    dv[jj] = unpack2(t);
                }
                float4 v0 = make_float4(dv[0].x, dv[1].x, dv[2].x, dv[3].x);
                float4 v1 = make_float4(dv[0].y, dv[1].y, dv[2].y, dv[3].y);
                const size_t ng = (size_t)n0 + nl + q * 4;
                *(float4*)(dist_out + (size_t)k0 * N_PTS + ng) = v0;
                *(float4*)(dist_out + (size_t)(k0 + 1) * N_PTS + ng) = v1;
                #pragma unroll
                for (int jj = 0; jj < 4; jj++) {
                    int j = q * 4 + jj;
                    float va = dv[jj].x, vb = dv[jj].y;
                    if (va < bd[j]) { bs[j] = bd[j]; bd[j] = va; bk[j] = k0; }
                    else if (va < bs[j]) bs[j] = va;
                    if (vb < bd[j]) { bs[j] = bd[j]; bd[j] = vb; bk[j] = k0 + 1; }
                    else if (vb < bs[j]) bs[j] = vb;
                }
            }
        }
    }

    // ---- simple, auditable reduce: dump (bd,bs,bk) to padded smem, scan ----
    __syncthreads();   // everyone done reading sA (GEMM) -> reuse for reduce
    float2* s_rd = (float2*)sA;                 // [128 cols][33 pad]
    int*    s_rk = (int*)(s_rd + 128 * 33);     // [128 cols][33 pad]
    #pragma unroll
    for (int j = 0; j < 8; j++) {
        s_rd[(nl + j) * 33 + tm] = make_float2(bd[j], bs[j]);
        s_rk[(nl + j) * 33 + tm] = bk[j];
    }
    __syncthreads();
    if (tid < 128) {
        float d1 = 3.4e38f, d2 = 3.4e38f;
        int k1 = 0;
        #pragma unroll 4
        for (int i = 0; i < 32; i++) {
            float2 v = s_rd[tid * 33 + i];
            int kk = s_rk[tid * 33 + i];
            if (v.x < d1) { d2 = fminf(d1, v.y); d1 = v.x; k1 = kk; }
            else          { d2 = fminf(d2, v.x); }
        }
        int n = n0 + tid;
        assign_out[n] = (float)k1;
        if (d2 - d1 < MARGIN) {
            g_best[n] = ~0ull;
            __threadfence();
            int slot = atomicAdd(&g_nflag, 1);
            g_flag[slot] = n;
        }
    }
}

// ------ exact-enough refinement: compensated fp32 (NO fp64 on B300!) -------
// One warp per (flagged point, 32-centroid block): 16 warps/point -> short
// dependency chains; combine via global atomicMin on packed (distbits, k).
static __device__ __forceinline__ void comp_accum(float a, float b,
                                                  float& sum, float& comp,
                                                  float& lo) {
    float s   = __fsub_rn(a, b);
    float z   = __fsub_rn(s, a);
    float err = __fsub_rn(__fsub_rn(a, __fsub_rn(s, z)), __fadd_rn(b, z));
    float p   = __fmul_rn(s, s);
    float pe  = __fmaf_rn(s, s, -p);
    lo  = __fmaf_rn(__fadd_rn(s, s), err, lo);
    lo  = __fadd_rn(lo, pe);
    float t = __fadd_rn(sum, p);
    comp = __fadd_rn(comp, __fadd_rn(__fsub_rn(sum, t), p));
    sum = t;
}

__global__ void __launch_bounds__(256, 2)
refine_kernel(const float* __restrict__ inp, const float* __restrict__ cen)
{
    __shared__ float sx[8][D_DIM];
    const int wid = threadIdx.x >> 5, l = threadIdx.x & 31;
    const int gw = blockIdx.x * 8 + wid;
    const int nW = gridDim.x * 8;
    const int nwork = g_nflag * 16;             // 16 warps per point
    for (int it = gw; it < nwork; it += nW) {
        const int fi = it >> 4, jb = it & 15;
        const int n = g_flag[fi];
        for (int d = l; d < D_DIM; d += 32)
            sx[wid][d] = inp[(size_t)n * D_DIM + d];
        __syncwarp();
        const int k = jb * 32 + l;
        const float4* c4 = (const float4*)(cen + (size_t)k * D_DIM);
        float sum = 0.0f, comp = 0.0f, lo = 0.0f;
        #pragma unroll 8
        for (int d4 = 0; d4 < D_DIM / 4; d4++) {
            float4 cv = __ldg(c4 + d4);
            const float* xp = &sx[wid][d4 * 4];
            comp_accum(xp[0], cv.x, sum, comp, lo);
            comp_accum(xp[1], cv.y, sum, comp, lo);
            comp_accum(xp[2], cv.z, sum, comp, lo);
            comp_accum(xp[3], cv.w, sum, comp, lo);
        }
        float dist = __fadd_rn(sum, __fadd_rn(comp, lo));
        ull e = ((ull)__float_as_uint(dist) << 32) | (unsigned)k;
        #pragma unroll
        for (int off = 16; off; off >>= 1) {
            ull oe = __shfl_xor_sync(0xffffffffu, e, off);
            if (oe < e) e = oe;
        }
        if (l == 0) atomicMin(&g_best[n], e);
        __syncwarp();
    }
}

__global__ void writeback_kernel(float* __restrict__ assign_out) {
    const int nf = g_nflag;
    for (int i = blockIdx.x * blockDim.x + threadIdx.x; i < nf;
         i += gridDim.x * blockDim.x) {
        int n = g_flag[i];
        assign_out[n] = (float)(unsigned)(g_best[n] & 0xffffffffu);
    }
}

// ---------------- launch ----------------
extern "C" void kernel_launch(void* const* d_in, const int* in_sizes, int n_in,
                              void* d_out, int out_size) {
    const float* inp = (const float*)d_in[0];
    const float* cen = (const float*)d_in[1];
    float* dist = (float*)d_out;
    long long need = (long long)K_CEN * N_PTS + N_PTS;
    float* assign = ((long long)out_size >= need) ? dist + (size_t)K_CEN * N_PTS
                                                  : dist;  // fallback, unused

    cudaFuncSetAttribute(kmeans_main, cudaFuncAttributeMaxDynamicSharedMemorySize,
                         SMEM_BYTES);

    transpose_c<<<dim3(K_CEN / 32, D_DIM / 32), 256>>>(cen);  // + zero flag ctr
    csq_kernel<<<K_CEN / 8, 256>>>(cen);                      // ||c||^2
    kmeans_main<<<N_PTS / 128, 512, SMEM_BYTES>>>(inp, dist, assign);
    refine_kernel<<<148, 256>>>(inp, cen);
    writeback_kernel<<<8, 256>>>(assign);
}

// round 11
// speedup vs baseline: 2.1710x; 1.0366x over previous
#include <cuda_runtime.h>
#include <cstdint>

typedef unsigned long long ull;

#define N_PTS 262144
#define K_CEN 512
#define D_DIM 128
#define MARGIN 0.006f
#define N_TILES (N_PTS / 128)

// scratch (device globals: allocation-free per harness rules)
__device__ float g_csq[K_CEN];
__device__ float g_ct[D_DIM * K_CEN];   // centroids transposed [d][k]
__device__ int   g_nflag;
__device__ int   g_flag[N_PTS];
__device__ ull   g_best[N_PTS];         // packed (distbits<<32)|k for flagged pts

// ---------------- packed f32x2 helpers (Blackwell FFMA2) ----------------
#define FMA2(d_, a_, b_) \
    asm("fma.rn.f32x2 %0, %1, %2, %0;" : "+l"(d_) : "l"(a_), "l"(b_))
#define ADD2(d_, a_, b_) \
    asm("add.rn.f32x2 %0, %1, %2;" : "=l"(d_) : "l"(a_), "l"(b_))
static __device__ __forceinline__ ull pack2(float lo, float hi) {
    ull r; asm("mov.b64 %0, {%1, %2};" : "=l"(r) : "f"(lo), "f"(hi)); return r;
}
static __device__ __forceinline__ float2 unpack2(ull v) {
    float2 r; asm("mov.b64 {%0, %1}, %2;" : "=f"(r.x), "=f"(r.y) : "l"(v)); return r;
}
// broadcast-duplicate via PRMT (alu pipe, keeps fma pipe pure FFMA2)
static __device__ __forceinline__ ull dup2(float x) {
    ull r; uint32_t xi = __float_as_uint(x);
    asm("{\n\t.reg .b32 lo, hi;\n\t"
        "prmt.b32 lo, %1, %1, 0x3210;\n\t"
        "prmt.b32 hi, %1, %1, 0x7654;\n\t"
        "mov.b64 %0, {lo, hi};\n\t}"
        : "=l"(r) : "r"(xi));
    return r;
}

// ------- fused prologue: centroid transpose + centroid norms + flag zero ----
// grid 64 x 256 thr. Block b: transpose subtile (n0 = (b&15)*32, d0 = (b>>4)*32)
// AND ||c||^2 for rows 8b..8b+7 (one warp per row).
__global__ void prep_kernel(const float* __restrict__ src) {
    if (blockIdx.x == 0 && threadIdx.x == 0) g_nflag = 0;
    __shared__ float t[32][33];
    const int tid = threadIdx.x;
    // --- csq part: warp w handles row blockIdx.x*8 + w ---
    {
        int w = blockIdx.x * 8 + (tid >> 5);
        int l = tid & 31;
        float4 v = *(const float4*)(src + (size_t)w * D_DIM + l * 4);
        float s = v.x * v.x + v.y * v.y + v.z * v.z + v.w * v.w;
        #pragma unroll
        for (int o = 16; o; o >>= 1) s += __shfl_xor_sync(0xffffffffu, s, o);
        if (l == 0) g_csq[w] = s;
    }
    // --- transpose part ---
    int n0 = (blockIdx.x & 15) * 32, d0 = (blockIdx.x >> 4) * 32;
    int tx = tid & 31, ty = tid >> 5;   // 256 thr: ty 0..7
    #pragma unroll
    for (int i = 0; i < 4; i++)
        t[ty + i * 8][tx] = src[(size_t)(n0 + ty + i * 8) * D_DIM + d0 + tx];
    __syncthreads();
    #pragma unroll
    for (int i = 0; i < 4; i++)
        g_ct[(size_t)(d0 + ty + i * 8) * K_CEN + n0 + tx] = t[tx][ty + i * 8];
}

// ---------------- main kernel (persistent) ----------------
// 152 CTAs loop over 2048 tiles. Per tile: 128 points (n) x 512 centroids
// (2 passes of 256 m), 512 threads. Thread tile: 8 m x 8 n.
// smem: sX [128 d][128 n] (64KB), sA [128 d][256 m] (128KB, reused for
// transpose staging + reduce), s_csq loaded ONCE per CTA.
#define SX_F   (128 * 128)
#define SA_F   (128 * 256)
#define SMEM_BYTES ((SX_F + SA_F + K_CEN + 128) * 4)

__global__ void __launch_bounds__(512, 1)
kmeans_main(const float* __restrict__ inp,
            float* __restrict__ dist_out, float* __restrict__ assign_out)
{
    extern __shared__ float sm[];
    float* sX    = sm;                 // [d][n] 128x128
    float* sA    = sX + SX_F;          // [d][m] 128x256 (GEMM) / staging / reduce
    float* s_csq = sA + SA_F;          // 512 (persistent across tiles)
    float* s_xsq = s_csq + K_CEN;      // 128

    const int tid = threadIdx.x;
    const int tn = tid & 15, tm = tid >> 4;     // 16 n-threads x 32 m-threads
    const int nl = tn * 8;                      // local col base (8 n per thread)

    s_csq[tid] = g_csq[tid];                    // once per CTA (tid < 512 = K_CEN)

    for (int tile = blockIdx.x; tile < N_TILES; tile += gridDim.x) {
        const int n0 = tile * 128;

        // ---- prologue: MLP-preload X tile, derive ||x||^2, transpose ----
        {
            const int r = tid >> 3, c4 = (tid & 7) * 4;    // read mapping
            const int tx = tid & 63, rg = tid >> 6;        // write mapping
            float4 vreg[8];
            #pragma unroll
            for (int st = 0; st < 8; st++) {               // 8 LDGs in flight
                int sn = st & 1, sd = st >> 1;             // subtile: 64 n x 32 d
                vreg[st] = *(const float4*)(inp +
                    (size_t)(n0 + sn * 64 + r) * D_DIM + sd * 32 + c4);
            }
            // ||x||^2 partials: even st -> row r, odd -> row r+64
            float px0 = 0.0f, px1 = 0.0f;
            #pragma unroll
            for (int st = 0; st < 8; st++) {
                float4 v = vreg[st];
                float s = fmaf(v.x, v.x, fmaf(v.y, v.y, fmaf(v.z, v.z, v.w * v.w)));
                if (st & 1) px1 += s; else px0 += s;
            }
            #pragma unroll
            for (int off = 1; off <= 4; off <<= 1) {       // sum over 8-lane group
                px0 += __shfl_xor_sync(0xffffffffu, px0, off);
                px1 += __shfl_xor_sync(0xffffffffu, px1, off);
            }

            float (*stg)[33] = (float (*)[33])sA;          // 64x33 staging
            #pragma unroll
            for (int st = 0; st < 8; st++) {
                int sn = st & 1, sd = st >> 1;
                stg[r][c4 + 0] = vreg[st].x; stg[r][c4 + 1] = vreg[st].y;
                stg[r][c4 + 2] = vreg[st].z; stg[r][c4 + 3] = vreg[st].w;
                __syncthreads();
                #pragma unroll
                for (int j = 0; j < 4; j++)
                    sX[(sd * 32 + rg * 4 + j) * 128 + sn * 64 + tx] =
                        stg[tx][rg * 4 + j];
                __syncthreads();
            }
            if ((tid & 7) == 0) {                          // lane leader of group
                s_xsq[r] = px0;
                s_xsq[r + 64] = px1;
            }
        }
        __syncthreads();

        float bd[8], bs[8];
        int   bk[8];
        #pragma unroll
        for (int j = 0; j < 8; j++) { bd[j] = 3.4e38f; bs[j] = 3.4e38f; bk[j] = 0; }

        const float* pA = sA + tm * 8;
        const float* pB = sX + nl;

        for (int pass = 0; pass < 2; pass++) {
            const int m0 = pass * 256;
            // prefetch first half of sA chunk BEFORE the sync (no smem touched)
            float4 pf[8];
            #pragma unroll
            for (int i = 0; i < 8; i++) {
                int idx = tid + i * 512;
                int d = idx >> 6, mq = (idx & 63) * 4;
                pf[i] = *(const float4*)(g_ct + (size_t)d * K_CEN + m0 + mq);
            }
            if (pass) __syncthreads();   // all warps done reading sA of pass 0
            #pragma unroll
            for (int i = 0; i < 8; i++) {
                int idx = tid + i * 512;
                int d = idx >> 6, mq = (idx & 63) * 4;
                *(float4*)(sA + d * 256 + mq) = pf[i];
            }
            #pragma unroll
            for (int i = 8; i < 16; i++) {
                int idx = tid + i * 512;
                int d = idx >> 6, mq = (idx & 63) * 4;
                *(float4*)(sA + d * 256 + mq) =
                    *(const float4*)(g_ct + (size_t)d * K_CEN + m0 + mq);
            }
            __syncthreads();

            ull acc[4][8];
            #pragma unroll
            for (int mp = 0; mp < 4; mp++)
                #pragma unroll
                for (int j = 0; j < 8; j++) acc[mp][j] = 0ull;

            #pragma unroll 4
            for (int d = 0; d < D_DIM; d++) {
                ulonglong2 A0 = *(const ulonglong2*)(pA + d * 256);
                ulonglong2 A1 = *(const ulonglong2*)(pA + d * 256 + 4);
                float4 b0 = *(const float4*)(pB + d * 128);
                float4 b1 = *(const float4*)(pB + d * 128 + 4);
                ull u;
                u = dup2(b0.x);
                FMA2(acc[0][0], A0.x, u); FMA2(acc[1][0], A0.y, u);
                FMA2(acc[2][0], A1.x, u); FMA2(acc[3][0], A1.y, u);
                u = dup2(b0.y);
                FMA2(acc[0][1], A0.x, u); FMA2(acc[1][1], A0.y, u);
                FMA2(acc[2][1], A1.x, u); FMA2(acc[3][1], A1.y, u);
                u = dup2(b0.z);
                FMA2(acc[0][2], A0.x, u); FMA2(acc[1][2], A0.y, u);
                FMA2(acc[2][2], A1.x, u); FMA2(acc[3][2], A1.y, u);
                u = dup2(b0.w);
                FMA2(acc[0][3], A0.x, u); FMA2(acc[1][3], A0.y, u);
                FMA2(acc[2][3], A1.x, u); FMA2(acc[3][3], A1.y, u);
                u = dup2(b1.x);
                FMA2(acc[0][4], A0.x, u); FMA2(acc[1][4], A0.y, u);
                FMA2(acc[2][4], A1.x, u); FMA2(acc[3][4], A1.y, u);
                u = dup2(b1.y);
                FMA2(acc[0][5], A0.x, u); FMA2(acc[1][5], A0.y, u);
                FMA2(acc[2][5], A1.x, u); FMA2(acc[3][5], A1.y, u);
                u = dup2(b1.z);
                FMA2(acc[0][6], A0.x, u); FMA2(acc[1][6], A0.y, u);
                FMA2(acc[2][6], A1.x, u); FMA2(acc[3][6], A1.y, u);
                u = dup2(b1.w);
                FMA2(acc[0][7], A0.x, u); FMA2(acc[1][7], A0.y, u);
                FMA2(acc[2][7], A1.x, u); FMA2(acc[3][7], A1.y, u);
            }

            // ---- epilogue: distances out + running best/second ----
            ull xsd[8];
            #pragma unroll
            for (int j = 0; j < 8; j++) xsd[j] = dup2(s_xsq[nl + j]);
            const ull neg2 = pack2(-2.0f, -2.0f);

            #pragma unroll
            for (int mp = 0; mp < 4; mp++) {
                const int k0 = m0 + tm * 8 + mp * 2;
                ull cs2 = pack2(s_csq[k0], s_csq[k0 + 1]);
                #pragma unroll
                for (int q = 0; q < 2; q++) {
                    float2 dv[4];
                    #pragma unroll
                    for (int jj = 0; jj < 4; jj++) {
                        int j = q * 4 + jj;
                        ull t; ADD2(t, cs2, xsd[j]);
                        FMA2(t, acc[mp][j], neg2);   // -2*dot + (c^2 + x^2)
                        dv[jj] = unpack2(t);
                    }
                    float4 v0 = make_float4(dv[0].x, dv[1].x, dv[2].x, dv[3].x);
                    float4 v1 = make_float4(dv[0].y, dv[1].y, dv[2].y, dv[3].y);
                    const size_t ng = (size_t)n0 + nl + q * 4;
                    *(float4*)(dist_out + (size_t)k0 * N_PTS + ng) = v0;
                    *(float4*)(dist_out + (size_t)(k0 + 1) * N_PTS + ng) = v1;
                    #pragma unroll
                    for (int jj = 0; jj < 4; jj++) {
                        int j = q * 4 + jj;
                        float va = dv[jj].x, vb = dv[jj].y;
                        if (va < bd[j]) { bs[j] = bd[j]; bd[j] = va; bk[j] = k0; }
                        else if (va < bs[j]) bs[j] = va;
                        if (vb < bd[j]) { bs[j] = bd[j]; bd[j] = vb; bk[j] = k0 + 1; }
                        else if (vb < bs[j]) bs[j] = vb;
                    }
                }
            }
        }

        // ---- reduce: dump (bd,bs,bk) to padded smem (sA region), scan ----
        __syncthreads();   // everyone done reading sA (GEMM) -> reuse for reduce
        float2* s_rd = (float2*)sA;                 // [128 cols][33 pad]
        int*    s_rk = (int*)(s_rd + 128 * 33);     // [128 cols][33 pad]
        #pragma unroll
        for (int j = 0; j < 8; j++) {
            s_rd[(nl + j) * 33 + tm] = make_float2(bd[j], bs[j]);
            s_rk[(nl + j) * 33 + tm] = bk[j];
        }
        __syncthreads();
        if (tid < 128) {
            float d1 = 3.4e38f, d2 = 3.4e38f;
            int k1 = 0;
            #pragma unroll 4
            for (int i = 0; i < 32; i++) {
                float2 v = s_rd[tid * 33 + i];
                int kk = s_rk[tid * 33 + i];
                if (v.x < d1) { d2 = fminf(d1, v.y); d1 = v.x; k1 = kk; }
                else          { d2 = fminf(d2, v.x); }
            }
            int n = n0 + tid;
            assign_out[n] = (float)k1;
            if (d2 - d1 < MARGIN) {
                g_best[n] = ~0ull;
                __threadfence();
                int slot = atomicAdd(&g_nflag, 1);
                g_flag[slot] = n;
            }
        }
        __syncthreads();   // scan readers done before next tile's staging writes
    }
}

// ------ exact-enough refinement: compensated fp32 (NO fp64 on B300!) -------
static __device__ __forceinline__ void comp_accum(float a, float b,
                                                  float& sum, float& comp,
                                                  float& lo) {
    float s   = __fsub_rn(a, b);
    float z   = __fsub_rn(s, a);
    float err = __fsub_rn(__fsub_rn(a, __fsub_rn(s, z)), __fadd_rn(b, z));
    float p   = __fmul_rn(s, s);
    float pe  = __fmaf_rn(s, s, -p);
    lo  = __fmaf_rn(__fadd_rn(s, s), err, lo);
    lo  = __fadd_rn(lo, pe);
    float t = __fadd_rn(sum, p);
    comp = __fadd_rn(comp, __fadd_rn(__fsub_rn(sum, t), p));
    sum = t;
}

__global__ void __launch_bounds__(256, 2)
refine_kernel(const float* __restrict__ inp, const float* __restrict__ cen)
{
    __shared__ float sx[8][D_DIM];
    const int wid = threadIdx.x >> 5, l = threadIdx.x & 31;
    const int gw = blockIdx.x * 8 + wid;
    const int nW = gridDim.x * 8;
    const int nwork = g_nflag * 16;             // 16 warps per point
    for (int it = gw; it < nwork; it += nW) {
        const int fi = it >> 4, jb = it & 15;
        const int n = g_flag[fi];
        for (int d = l; d < D_DIM; d += 32)
            sx[wid][d] = inp[(size_t)n * D_DIM + d];
        __syncwarp();
        const int k = jb * 32 + l;
        const float4* c4 = (const float4*)(cen + (size_t)k * D_DIM);
        float sum = 0.0f, comp = 0.0f, lo = 0.0f;
        #pragma unroll 8
        for (int d4 = 0; d4 < D_DIM / 4; d4++) {
            float4 cv = __ldg(c4 + d4);
            const float* xp = &sx[wid][d4 * 4];
            comp_accum(xp[0], cv.x, sum, comp, lo);
            comp_accum(xp[1], cv.y, sum, comp, lo);
            comp_accum(xp[2], cv.z, sum, comp, lo);
            comp_accum(xp[3], cv.w, sum, comp, lo);
        }
        float dist = __fadd_rn(sum, __fadd_rn(comp, lo));
        ull e = ((ull)__float_as_uint(dist) << 32) | (unsigned)k;
        #pragma unroll
        for (int off = 16; off; off >>= 1) {
            ull oe = __shfl_xor_sync(0xffffffffu, e, off);
            if (oe < e) e = oe;
        }
        if (l == 0) atomicMin(&g_best[n], e);
        __syncwarp();
    }
}

__global__ void writeback_kernel(float* __restrict__ assign_out) {
    const int nf = g_nflag;
    for (int i = blockIdx.x * blockDim.x + threadIdx.x; i < nf;
         i += gridDim.x * blockDim.x) {
        int n = g_flag[i];
        assign_out[n] = (float)(unsigned)(g_best[n] & 0xffffffffu);
    }
}

// ---------------- launch ----------------
extern "C" void kernel_launch(void* const* d_in, const int* in_sizes, int n_in,
                              void* d_out, int out_size) {
    const float* inp = (const float*)d_in[0];
    const float* cen = (const float*)d_in[1];
    float* dist = (float*)d_out;
    long long need = (long long)K_CEN * N_PTS + N_PTS;
    float* assign = ((long long)out_size >= need) ? dist + (size_t)K_CEN * N_PTS
                                                  : dist;  // fallback, unused

    cudaFuncSetAttribute(kmeans_main, cudaFuncAttributeMaxDynamicSharedMemorySize,
                         SMEM_BYTES);

    prep_kernel<<<64, 256>>>(cen);                       // transpose + csq + flag0
    kmeans_main<<<152, 512, SMEM_BYTES>>>(inp, dist, assign);  // persistent
    refine_kernel<<<152, 256>>>(inp, cen);
    writeback_kernel<<<8, 256>>>(assign);
}